// round 4
// baseline (speedup 1.0000x reference)
#include <cuda_runtime.h>

// BoxQueryAndGroup: B=4, N=16384, C=64, NQ=256, S=32
//
// Reference: idx_f = in_box * arange(N); stable argsort ascending, first 32.
// Zero-keys = {n : !in_box[n]} ∪ {0}; with N(0,1) points and half-sizes
// <= 0.75, >>32 zero-keys always exist, so the answer is the 32 smallest
// indices with (n==0 || !in_box), ascending. Pass 2 keeps exact argsort
// semantics in the (never-seen) case of <32 zero-keys.
// local_group_mask is identically False => 0.0f.
//
// Outputs concatenated flat, float32:
//   grouped_xyz  (B,3,NQ,S), new_features (B,67,NQ,S), mask (B,NQ,S)
//
// R3 design: one warp per (query, 8-channel group); 8 warps/query, all fully
// independent (each redundantly does the ~2-iteration scan on L1-resident
// data). No smem, no block barrier. All stores are STG.128.

#define BQ_B  4
#define BQ_N  16384
#define BQ_C  64
#define BQ_NQ 256
#define BQ_S  32

#define BQ_THREADS 256   // 8 warps / block; warps are independent

__global__ __launch_bounds__(BQ_THREADS)
void boxquery_group_kernel(const float* __restrict__ key_xyz,     // (B,N,3)
                           const float* __restrict__ key_feat,    // (B,C,N)
                           const float* __restrict__ query_box,   // (B,NQ,6)
                           float* __restrict__ out) {
    const int lane = threadIdx.x & 31;
    const int wid  = threadIdx.x >> 5;
    const int W    = blockIdx.x * (BQ_THREADS / 32) + wid;  // 0..8191
    const int qid  = W >> 3;          // 0..1023  (b*NQ + q)
    const int role = W & 7;           // channel group 0..7
    const int b    = qid >> 8;
    const int q    = qid & (BQ_NQ - 1);

    const float* qb = query_box + (size_t)qid * 6;
    const float cx = qb[0], cy = qb[1], cz = qb[2];
    const float hx = 0.5f * qb[3], hy = 0.5f * qb[4], hz = 0.5f * qb[5];

    const float* xyzb = key_xyz + (size_t)b * BQ_N * 3;

    // ---- Selection scan (every warp; ~2 iterations, L1-broadcast loads) ----
    int idx = 0;          // idx_sorted[lane]
    int count = 0;
    int base  = 0;
    while (count < BQ_S && base < BQ_N) {        // N % 32 == 0: n always valid
        const int n = base + lane;
        const float x = xyzb[n * 3 + 0];
        const float y = xyzb[n * 3 + 1];
        const float z = xyzb[n * 3 + 2];
        const bool inb = (fabsf(x - cx) <= hx) &&
                         (fabsf(y - cy) <= hy) &&
                         (fabsf(z - cz) <= hz);
        const bool cand = (n == 0) || !inb;
        const unsigned m = __ballot_sync(0xffffffffu, cand);
        const int pc = __popc(m);
        if (lane >= count && lane < count + pc) {
            idx = base + (int)__fns(m, 0, lane - count + 1);  // (lane-count+1)-th set bit
        }
        count += pc;
        base  += 32;
    }
    // Pass 2 (theoretical fallback): in-box indices n>0, key=n ascending.
    if (count < BQ_S) {
        base = 0;
        while (count < BQ_S && base < BQ_N) {
            const int n = base + lane;
            const float x = xyzb[n * 3 + 0];
            const float y = xyzb[n * 3 + 1];
            const float z = xyzb[n * 3 + 2];
            const bool cand = (n != 0) &&
                              (fabsf(x - cx) <= hx) &&
                              (fabsf(y - cy) <= hy) &&
                              (fabsf(z - cz) <= hz);
            const unsigned m = __ballot_sync(0xffffffffu, cand);
            const int pc = __popc(m);
            if (lane >= count && lane < count + pc) {
                idx = base + (int)__fns(m, 0, lane - count + 1);
            }
            count += pc;
            base  += 32;
        }
    }

    // Indices for the 4 samples this thread stores: s = 4j..4j+3, j = lane&7
    const int j = lane & 7;
    const int i0 = __shfl_sync(0xffffffffu, idx, 4 * j + 0);
    const int i1 = __shfl_sync(0xffffffffu, idx, 4 * j + 1);
    const int i2 = __shfl_sync(0xffffffffu, idx, 4 * j + 2);
    const int i3 = __shfl_sync(0xffffffffu, idx, 4 * j + 3);

    // Output sections
    float* gxyz = out;                                              // (B,3,NQ,S)
    float* nf   = out + (size_t)BQ_B * 3 * BQ_NQ * BQ_S;            // (B,67,NQ,S)
    float* mask = nf  + (size_t)BQ_B * (3 + BQ_C) * BQ_NQ * BQ_S;   // (B,NQ,S)
    const size_t plane = (size_t)BQ_NQ * BQ_S;
    const size_t qs4   = (size_t)q * BQ_S + 4 * j;   // float4-aligned offset

    // ---- xyz + mask (roles 0 and 1 only): one STG.128 per warp ----
    if (role < 2) {
        const int r = lane >> 3;                 // 0=gx,1=gy,2=gz,3=mask
        float4 v = make_float4(0.f, 0.f, 0.f, 0.f);
        if (r < 3) {
            const float cr = (r == 0) ? cx : (r == 1) ? cy : cz;
            v.x = xyzb[i0 * 3 + r] - cr;
            v.y = xyzb[i1 * 3 + r] - cr;
            v.z = xyzb[i2 * 3 + r] - cr;
            v.w = xyzb[i3 * 3 + r] - cr;
        }
        if (role == 0) {
            float* p = (r < 3) ? (gxyz + ((size_t)b * 3 + r) * plane + qs4)
                               : (mask + (size_t)b * plane + qs4);
            *(float4*)p = v;
        } else {
            if (r < 3) {
                float* p = nf + ((size_t)b * (3 + BQ_C) + r) * plane + qs4;
                *(float4*)p = v;
            }
        }
    }

    // ---- Features: 8 channels per warp, 2 STG.128 passes ----
    const float* fb = key_feat + (size_t)b * BQ_C * BQ_N;
    const int c0 = role * 8;
    #pragma unroll
    for (int p = 0; p < 2; p++) {
        const int c = c0 + p * 4 + (lane >> 3);
        const float* fr = fb + (size_t)c * BQ_N;
        float4 v;
        v.x = __ldg(fr + i0);
        v.y = __ldg(fr + i1);
        v.z = __ldg(fr + i2);
        v.w = __ldg(fr + i3);
        *(float4*)(nf + ((size_t)b * (3 + BQ_C) + 3 + c) * plane + qs4) = v;
    }
}

extern "C" void kernel_launch(void* const* d_in, const int* in_sizes, int n_in,
                              void* d_out, int out_size) {
    const float* key_xyz   = (const float*)d_in[0];
    const float* key_feat  = (const float*)d_in[1];
    const float* query_box = (const float*)d_in[2];
    float* out = (float*)d_out;

    // 8 warps per query, 8 warps per block -> one block per query
    boxquery_group_kernel<<<BQ_B * BQ_NQ, BQ_THREADS>>>(key_xyz, key_feat,
                                                        query_box, out);
}

// round 5
// speedup vs baseline: 1.0257x; 1.0257x over previous
#include <cuda_runtime.h>

// BoxQueryAndGroup: B=4, N=16384, C=64, NQ=256, S=32
//
// Reference: idx_f = in_box * arange(N); stable argsort ascending, first 32.
// Zero-keys = {n : !in_box[n]} ∪ {0}; the answer is the 32 smallest indices
// with (n==0 || !in_box), ascending. Fallback loops keep exact argsort
// semantics if fewer than 32 zero-keys exist (never observed).
// local_group_mask is identically False => 0.0f.
//
// Outputs concatenated flat, float32:
//   grouped_xyz (B,3,NQ,S), new_features (B,67,NQ,S), mask (B,NQ,S)
//
// R4: one block per query. Warp 0 does ONE unrolled 64-point selection scan
// into smem; after the barrier all 8 warps emit STG.128-only output
// (features 8 ch/warp; roles 0/1 also cover xyz+mask rows).

#define BQ_B  4
#define BQ_N  16384
#define BQ_C  64
#define BQ_NQ 256
#define BQ_S  32

#define BQ_THREADS 256

__global__ __launch_bounds__(BQ_THREADS)
void boxquery_group_kernel(const float* __restrict__ key_xyz,     // (B,N,3)
                           const float* __restrict__ key_feat,    // (B,C,N)
                           const float* __restrict__ query_box,   // (B,NQ,6)
                           float* __restrict__ out) {
    const int lane = threadIdx.x & 31;
    const int role = threadIdx.x >> 5;          // warp id == role 0..7
    const int qid  = blockIdx.x;                // b*NQ + q
    const int b    = qid >> 8;
    const int q    = qid & (BQ_NQ - 1);

    __shared__ int s_idx[BQ_S];

    // Every warp loads the box up-front (L1-broadcast; independent of scan).
    const float* qb = query_box + (size_t)qid * 6;
    const float cx = qb[0], cy = qb[1], cz = qb[2];
    const float hx = 0.5f * qb[3], hy = 0.5f * qb[4], hz = 0.5f * qb[5];

    const float* xyzb = key_xyz + (size_t)b * BQ_N * 3;

    // ---- Selection: warp 0 only, unrolled 64-point fast path ----
    if (role == 0) {
        s_idx[lane] = 0;
        __syncwarp();

        const int n1 = lane + 32;
        const float x0 = xyzb[lane * 3 + 0];
        const float y0 = xyzb[lane * 3 + 1];
        const float z0 = xyzb[lane * 3 + 2];
        const float x1 = xyzb[n1 * 3 + 0];
        const float y1 = xyzb[n1 * 3 + 1];
        const float z1 = xyzb[n1 * 3 + 2];

        const bool inb0 = (fabsf(x0 - cx) <= hx) && (fabsf(y0 - cy) <= hy) &&
                          (fabsf(z0 - cz) <= hz);
        const bool inb1 = (fabsf(x1 - cx) <= hx) && (fabsf(y1 - cy) <= hy) &&
                          (fabsf(z1 - cz) <= hz);
        const bool cand0 = (lane == 0) || !inb0;
        const bool cand1 = !inb1;

        const unsigned m0 = __ballot_sync(0xffffffffu, cand0);
        const unsigned m1 = __ballot_sync(0xffffffffu, cand1);
        const int c0 = __popc(m0);
        const int c1 = __popc(m1);

        int idx = -1;
        if (lane < c0) {
            idx = (int)__fns(m0, 0, lane + 1);
        } else if (lane - c0 < c1) {
            idx = 32 + (int)__fns(m1, 0, lane - c0 + 1);
        }
        if (idx >= 0) s_idx[lane] = idx;

        int count = c0 + c1;
        // Slow continuation (statistically never taken): finish zero-keys.
        if (count < BQ_S) {
            int base = 64;
            while (count < BQ_S && base < BQ_N) {
                const int n = base + lane;
                const float x = xyzb[n * 3 + 0];
                const float y = xyzb[n * 3 + 1];
                const float z = xyzb[n * 3 + 2];
                const bool cand = !((fabsf(x - cx) <= hx) &&
                                    (fabsf(y - cy) <= hy) &&
                                    (fabsf(z - cz) <= hz));
                const unsigned m = __ballot_sync(0xffffffffu, cand);
                const int slot = count + __popc(m & ((1u << lane) - 1u));
                if (cand && slot < BQ_S) s_idx[slot] = n;
                count += __popc(m);
                base  += 32;
            }
            // Pass 2: in-box indices n>0, key=n ascending.
            if (count < BQ_S) {
                base = 0;
                while (count < BQ_S && base < BQ_N) {
                    const int n = base + lane;
                    const float x = xyzb[n * 3 + 0];
                    const float y = xyzb[n * 3 + 1];
                    const float z = xyzb[n * 3 + 2];
                    const bool cand = (n != 0) &&
                                      (fabsf(x - cx) <= hx) &&
                                      (fabsf(y - cy) <= hy) &&
                                      (fabsf(z - cz) <= hz);
                    const unsigned m = __ballot_sync(0xffffffffu, cand);
                    const int slot = count + __popc(m & ((1u << lane) - 1u));
                    if (cand && slot < BQ_S) s_idx[slot] = n;
                    count += __popc(m);
                    base  += 32;
                }
            }
        }
    }
    __syncthreads();

    // ---- Consumers: STG.128-only output ----
    const int j = lane & 7;                 // float4 slot: samples 4j..4j+3
    const int i0 = s_idx[4 * j + 0];
    const int i1 = s_idx[4 * j + 1];
    const int i2 = s_idx[4 * j + 2];
    const int i3 = s_idx[4 * j + 3];

    float* gxyz = out;                                              // (B,3,NQ,S)
    float* nf   = out + (size_t)BQ_B * 3 * BQ_NQ * BQ_S;            // (B,67,NQ,S)
    float* mask = nf  + (size_t)BQ_B * (3 + BQ_C) * BQ_NQ * BQ_S;   // (B,NQ,S)
    const size_t plane = (size_t)BQ_NQ * BQ_S;
    const size_t qs4   = (size_t)q * BQ_S + 4 * j;

    if (role < 2) {
        const int r = lane >> 3;            // 0=gx 1=gy 2=gz 3=mask
        float4 v = make_float4(0.f, 0.f, 0.f, 0.f);
        if (r < 3) {
            const float cr = (r == 0) ? cx : (r == 1) ? cy : cz;
            v.x = xyzb[i0 * 3 + r] - cr;
            v.y = xyzb[i1 * 3 + r] - cr;
            v.z = xyzb[i2 * 3 + r] - cr;
            v.w = xyzb[i3 * 3 + r] - cr;
        }
        if (role == 0) {
            float* p = (r < 3) ? (gxyz + ((size_t)b * 3 + r) * plane + qs4)
                               : (mask + (size_t)b * plane + qs4);
            *(float4*)p = v;
        } else if (r < 3) {
            *(float4*)(nf + ((size_t)b * (3 + BQ_C) + r) * plane + qs4) = v;
        }
    }

    // Features: 8 channels per warp, 2 STG.128 per warp.
    const float* fb = key_feat + (size_t)b * BQ_C * BQ_N;
    const int c0ch = role * 8;
    #pragma unroll
    for (int p = 0; p < 2; p++) {
        const int c = c0ch + p * 4 + (lane >> 3);
        const float* fr = fb + (size_t)c * BQ_N;
        float4 v;
        v.x = __ldg(fr + i0);
        v.y = __ldg(fr + i1);
        v.z = __ldg(fr + i2);
        v.w = __ldg(fr + i3);
        *(float4*)(nf + ((size_t)b * (3 + BQ_C) + 3 + c) * plane + qs4) = v;
    }
}

extern "C" void kernel_launch(void* const* d_in, const int* in_sizes, int n_in,
                              void* d_out, int out_size) {
    const float* key_xyz   = (const float*)d_in[0];
    const float* key_feat  = (const float*)d_in[1];
    const float* query_box = (const float*)d_in[2];
    float* out = (float*)d_out;

    boxquery_group_kernel<<<BQ_B * BQ_NQ, BQ_THREADS>>>(key_xyz, key_feat,
                                                        query_box, out);
}